// round 1
// baseline (speedup 1.0000x reference)
#include <cuda_runtime.h>
#include <math.h>

#define FDIM 1024
#define TSEQ 2048
#define BATCH 2
#define NH 16
#define HD 64
#define ROWS (BATCH*TSEQ)   // 4096
#define STR 68              // padded smem stride (floats), 272B rows -> float4 aligned
#define ATT_SMEM (3*64*STR*4)

// scratch (allocation-free rule: __device__ globals)
__device__ float g_xn[ROWS*FDIM];
__device__ float g_q[ROWS*FDIM];
__device__ float g_kv[ROWS*2*HD];
__device__ float g_att[ROWS*FDIM];

// ---------------- LayerNorm ----------------
__global__ void ln_kernel(const float* __restrict__ x, const float* __restrict__ gamma,
                          const float* __restrict__ beta, float* __restrict__ xn) {
    int row = blockIdx.x;
    const float* xr = x + (size_t)row * FDIM;
    float s = 0.f, s2 = 0.f;
    for (int i = threadIdx.x; i < FDIM; i += 256) { float v = xr[i]; s += v; s2 += v * v; }
    __shared__ float rs[8], rs2[8];
    for (int o = 16; o > 0; o >>= 1) {
        s  += __shfl_xor_sync(0xffffffffu, s,  o);
        s2 += __shfl_xor_sync(0xffffffffu, s2, o);
    }
    int w = threadIdx.x >> 5;
    if ((threadIdx.x & 31) == 0) { rs[w] = s; rs2[w] = s2; }
    __syncthreads();
    if (threadIdx.x < 32) {
        s  = (threadIdx.x < 8) ? rs[threadIdx.x]  : 0.f;
        s2 = (threadIdx.x < 8) ? rs2[threadIdx.x] : 0.f;
        for (int o = 4; o > 0; o >>= 1) {
            s  += __shfl_xor_sync(0xffffffffu, s,  o);
            s2 += __shfl_xor_sync(0xffffffffu, s2, o);
        }
        if (threadIdx.x == 0) { rs[0] = s; rs2[0] = s2; }
    }
    __syncthreads();
    float mu  = rs[0] * (1.f / FDIM);
    float var = rs2[0] * (1.f / FDIM) - mu * mu;
    float inv = rsqrtf(var + 1e-5f);
    float* xo = xn + (size_t)row * FDIM;
    for (int i = threadIdx.x; i < FDIM; i += 256)
        xo[i] = (xr[i] - mu) * inv * gamma[i] + beta[i];
}

// ---------------- Tiled fp32 GEMM: C[M,N] = A[M,K] @ B[K,N] (+bias +resid) ----------------
// BM=BN=64, BK=16, 256 threads, 4x4 micro-tile. M,N multiples of 64; K multiple of 16.
__global__ void gemm64_kernel(const float* __restrict__ A, const float* __restrict__ Bm,
                              float* __restrict__ C, int M, int N, int K,
                              const float* __restrict__ bias, const float* __restrict__ resid) {
    __shared__ float As[16][64];  // As[k][m]
    __shared__ float Bs[16][64];  // Bs[k][n]
    int tid = threadIdx.x;
    int tx = tid & 15, ty = tid >> 4;
    int n0 = blockIdx.x * 64, m0 = blockIdx.y * 64;
    float acc[4][4] = {};
    int lm = tid >> 2, lk = (tid & 3) * 4;     // A tile load coords
    int lbk = tid >> 4, lbn = (tid & 15) * 4;  // B tile load coords

    for (int k0 = 0; k0 < K; k0 += 16) {
        float4 av = *(const float4*)(A  + (size_t)(m0 + lm) * K + k0 + lk);
        float4 bv = *(const float4*)(Bm + (size_t)(k0 + lbk) * N + n0 + lbn);
        As[lk + 0][lm] = av.x; As[lk + 1][lm] = av.y;
        As[lk + 2][lm] = av.z; As[lk + 3][lm] = av.w;
        *(float4*)&Bs[lbk][lbn] = bv;
        __syncthreads();
#pragma unroll
        for (int kk = 0; kk < 16; kk++) {
            float ar[4], br[4];
            *(float4*)ar = *(const float4*)&As[kk][ty * 4];
            *(float4*)br = *(const float4*)&Bs[kk][tx * 4];
#pragma unroll
            for (int i = 0; i < 4; i++)
#pragma unroll
                for (int j = 0; j < 4; j++)
                    acc[i][j] += ar[i] * br[j];
        }
        __syncthreads();
    }
#pragma unroll
    for (int i = 0; i < 4; i++) {
        int row = m0 + ty * 4 + i;
#pragma unroll
        for (int j = 0; j < 4; j++) {
            int col = n0 + tx * 4 + j;
            float v = acc[i][j];
            if (bias)  v += bias[col];
            if (resid) v += resid[(size_t)row * N + col];
            C[(size_t)row * N + col] = v;
        }
    }
}

// ---------------- Flash-style MQA attention ----------------
// Grid: (T/64, H, B), 256 threads. Q: [ROWS, F] (head h at col h*64). KV: [ROWS, 128] (K cols 0..63, V 64..127)
__global__ void attn_kernel(const float* __restrict__ Q, const float* __restrict__ KV,
                            float* __restrict__ O) {
    extern __shared__ float sm[];
    float* Qs = sm;               // transposed: Qs[d*STR + qrow]
    float* Ks = sm + 64 * STR;    // K transposed Ks[d*STR + s]; reused for V natural Vs[s*STR + c]
    float* Ps = sm + 2 * 64 * STR;// Ps[r*STR + s]
    int tid = threadIdx.x;
    int tx = tid & 15, ty = tid >> 4;
    int q0 = blockIdx.x * 64;
    int h = blockIdx.y, b = blockIdx.z;
    const float* Qb = Q + ((size_t)(b * TSEQ + q0)) * FDIM + h * HD;
    const float* Kb = KV + (size_t)b * TSEQ * (2 * HD);

    { // load Q tile (64 queries x 64 dims) transposed into smem
        int r = tid >> 4, f = tid & 15;
#pragma unroll
        for (int i = 0; i < 4; i++) {
            int row = r + 16 * i;
            float4 v = *(const float4*)(Qb + (size_t)row * FDIM + f * 4);
            Qs[(f * 4 + 0) * STR + row] = v.x; Qs[(f * 4 + 1) * STR + row] = v.y;
            Qs[(f * 4 + 2) * STR + row] = v.z; Qs[(f * 4 + 3) * STR + row] = v.w;
        }
    }
    float m_i[4], l_i[4], o[4][4];
#pragma unroll
    for (int i = 0; i < 4; i++) {
        m_i[i] = -1e30f; l_i[i] = 0.f;
#pragma unroll
        for (int j = 0; j < 4; j++) o[i][j] = 0.f;
    }
    const float scale = 0.125f;  // 1/sqrt(64)
    __syncthreads();

    for (int kb = 0; kb < TSEQ / 64; kb++) {
        const float* Kt = Kb + (size_t)kb * 64 * (2 * HD);
        { // load K tile transposed: Ks[d][s]
            int r = tid >> 4, f = tid & 15;
#pragma unroll
            for (int i = 0; i < 4; i++) {
                int row = r + 16 * i;
                float4 v = *(const float4*)(Kt + (size_t)row * (2 * HD) + f * 4);
                Ks[(f * 4 + 0) * STR + row] = v.x; Ks[(f * 4 + 1) * STR + row] = v.y;
                Ks[(f * 4 + 2) * STR + row] = v.z; Ks[(f * 4 + 3) * STR + row] = v.w;
            }
        }
        __syncthreads();

        float s[4][4] = {};
#pragma unroll 8
        for (int d = 0; d < 64; d++) {
            float qr[4], kr[4];
            *(float4*)qr = *(const float4*)&Qs[d * STR + ty * 4];
            *(float4*)kr = *(const float4*)&Ks[d * STR + tx * 4];
#pragma unroll
            for (int i = 0; i < 4; i++)
#pragma unroll
                for (int j = 0; j < 4; j++)
                    s[i][j] += qr[i] * kr[j];
        }

        // online softmax (rows r = 4*ty+i; the 16 threads of a row share a half-warp)
#pragma unroll
        for (int i = 0; i < 4; i++) {
            float mx = fmaxf(fmaxf(s[i][0], s[i][1]), fmaxf(s[i][2], s[i][3])) * scale;
            for (int ofs = 8; ofs > 0; ofs >>= 1)
                mx = fmaxf(mx, __shfl_xor_sync(0xffffffffu, mx, ofs));
            float mnew = fmaxf(m_i[i], mx);
            float alpha = __expf(m_i[i] - mnew);
            float sum = 0.f;
#pragma unroll
            for (int j = 0; j < 4; j++) {
                float p = __expf(s[i][j] * scale - mnew);
                Ps[(ty * 4 + i) * STR + tx * 4 + j] = p;
                sum += p;
            }
            for (int ofs = 8; ofs > 0; ofs >>= 1)
                sum += __shfl_xor_sync(0xffffffffu, sum, ofs);
            l_i[i] = l_i[i] * alpha + sum;
            m_i[i] = mnew;
#pragma unroll
            for (int j = 0; j < 4; j++) o[i][j] *= alpha;
        }
        __syncthreads();  // S-compute reads of Ks done; Ps fully written

        { // load V tile natural layout: Vs[s][c] into Ks buffer
            int r = tid >> 4, f = tid & 15;
#pragma unroll
            for (int i = 0; i < 4; i++) {
                int row = r + 16 * i;
                float4 v = *(const float4*)(Kt + (size_t)row * (2 * HD) + HD + f * 4);
                *(float4*)&Ks[row * STR + f * 4] = v;
            }
        }
        __syncthreads();

#pragma unroll 8
        for (int sidx = 0; sidx < 64; sidx++) {
            float vr[4];
            *(float4*)vr = *(const float4*)&Ks[sidx * STR + tx * 4];
#pragma unroll
            for (int i = 0; i < 4; i++) {
                float p = Ps[(ty * 4 + i) * STR + sidx];
#pragma unroll
                for (int j = 0; j < 4; j++) o[i][j] += p * vr[j];
            }
        }
        __syncthreads();  // PV reads done before next tile overwrites
    }

#pragma unroll
    for (int i = 0; i < 4; i++) {
        float inv = 1.f / l_i[i];
        int row = q0 + ty * 4 + i;
        float* orow = O + ((size_t)(b * TSEQ + row)) * FDIM + h * HD;
#pragma unroll
        for (int j = 0; j < 4; j++)
            orow[tx * 4 + j] = o[i][j] * inv;
    }
}

extern "C" void kernel_launch(void* const* d_in, const int* in_sizes, int n_in,
                              void* d_out, int out_size) {
    (void)in_sizes; (void)n_in; (void)out_size;
    const float* x     = (const float*)d_in[0];
    const float* gamma = (const float*)d_in[1];
    const float* beta  = (const float*)d_in[2];
    const float* Wq    = (const float*)d_in[3];
    const float* Wkv   = (const float*)d_in[4];
    const float* Wo    = (const float*)d_in[5];
    const float* bo    = (const float*)d_in[6];
    float* out = (float*)d_out;

    float *xn, *q, *kv, *att;
    cudaGetSymbolAddress((void**)&xn,  g_xn);
    cudaGetSymbolAddress((void**)&q,   g_q);
    cudaGetSymbolAddress((void**)&kv,  g_kv);
    cudaGetSymbolAddress((void**)&att, g_att);

    ln_kernel<<<ROWS, 256>>>(x, gamma, beta, xn);

    gemm64_kernel<<<dim3(FDIM / 64, ROWS / 64), 256>>>(xn, Wq, q, ROWS, FDIM, FDIM, nullptr, nullptr);
    gemm64_kernel<<<dim3((2 * HD) / 64, ROWS / 64), 256>>>(xn, Wkv, kv, ROWS, 2 * HD, FDIM, nullptr, nullptr);

    cudaFuncSetAttribute(attn_kernel, cudaFuncAttributeMaxDynamicSharedMemorySize, ATT_SMEM);
    attn_kernel<<<dim3(TSEQ / 64, NH, BATCH), 256, ATT_SMEM>>>(q, kv, att);

    gemm64_kernel<<<dim3(FDIM / 64, ROWS / 64), 256>>>(att, Wo, out, ROWS, FDIM, FDIM, bo, x);
}

// round 2
// speedup vs baseline: 2.9803x; 2.9803x over previous
#include <cuda_runtime.h>
#include <math.h>

#define FDIM 1024
#define TSEQ 2048
#define BATCH 2
#define NH 16
#define HD 64
#define ROWS (BATCH*TSEQ)   // 4096

// scratch (allocation-free rule: __device__ globals)
__device__ float g_xn[ROWS*FDIM];
__device__ float g_q[ROWS*FDIM];
__device__ float g_kv[ROWS*2*HD];
__device__ float g_att[ROWS*FDIM];

// ---------- helpers ----------
__device__ __forceinline__ unsigned f2tf(float f) {
    unsigned u; asm("cvt.rna.tf32.f32 %0, %1;" : "=r"(u) : "f"(f)); return u;
}
__device__ __forceinline__ void mma_tf32(float* c, const unsigned* a, const unsigned* b) {
    asm volatile(
        "mma.sync.aligned.m16n8k8.row.col.f32.tf32.tf32.f32 "
        "{%0,%1,%2,%3},{%4,%5,%6,%7},{%8,%9},{%0,%1,%2,%3};"
        : "+f"(c[0]), "+f"(c[1]), "+f"(c[2]), "+f"(c[3])
        : "r"(a[0]), "r"(a[1]), "r"(a[2]), "r"(a[3]), "r"(b[0]), "r"(b[1]));
}

// ---------------- LayerNorm ----------------
__global__ void ln_kernel(const float* __restrict__ x, const float* __restrict__ gamma,
                          const float* __restrict__ beta, float* __restrict__ xn) {
    int row = blockIdx.x;
    const float* xr = x + (size_t)row * FDIM;
    float s = 0.f, s2 = 0.f;
    for (int i = threadIdx.x; i < FDIM; i += 256) { float v = xr[i]; s += v; s2 += v * v; }
    __shared__ float rs[8], rs2[8];
    for (int o = 16; o > 0; o >>= 1) {
        s  += __shfl_xor_sync(0xffffffffu, s,  o);
        s2 += __shfl_xor_sync(0xffffffffu, s2, o);
    }
    int w = threadIdx.x >> 5;
    if ((threadIdx.x & 31) == 0) { rs[w] = s; rs2[w] = s2; }
    __syncthreads();
    if (threadIdx.x < 32) {
        s  = (threadIdx.x < 8) ? rs[threadIdx.x]  : 0.f;
        s2 = (threadIdx.x < 8) ? rs2[threadIdx.x] : 0.f;
        for (int o = 4; o > 0; o >>= 1) {
            s  += __shfl_xor_sync(0xffffffffu, s,  o);
            s2 += __shfl_xor_sync(0xffffffffu, s2, o);
        }
        if (threadIdx.x == 0) { rs[0] = s; rs2[0] = s2; }
    }
    __syncthreads();
    float mu  = rs[0] * (1.f / FDIM);
    float var = rs2[0] * (1.f / FDIM) - mu * mu;
    float inv = rsqrtf(var + 1e-5f);
    float* xo = xn + (size_t)row * FDIM;
    for (int i = threadIdx.x; i < FDIM; i += 256)
        xo[i] = (xr[i] - mu) * inv * gamma[i] + beta[i];
}

// ---------------- TF32 tensor-core GEMM: C[M,N] = A[M,K] @ B[K,N] (+bias +resid) ----------------
// CTA tile 128(M) x 64(N), BK=32, 256 threads = 8 warps in 4(m) x 2(n).
// Warp computes 32x32 via m16n8k8: 2 m-tiles x 4 n-tiles.
#define ASTR 36
#define BSTR 72
__global__ __launch_bounds__(256) void gemm_tc_kernel(
    const float* __restrict__ A, const float* __restrict__ Bm,
    float* __restrict__ C, int M, int N, int K,
    const float* __restrict__ bias, const float* __restrict__ resid) {
    __shared__ float As[128 * ASTR];
    __shared__ float Bs[32 * BSTR];
    int tid = threadIdx.x;
    int lane = tid & 31, wid = tid >> 5;
    int g = lane >> 2, tig = lane & 3;
    int wm = (wid & 3) * 32, wn = (wid >> 2) * 32;
    int m0 = blockIdx.y * 128, n0 = blockIdx.x * 64;

    float acc[2][4][4];
#pragma unroll
    for (int mt = 0; mt < 2; mt++)
#pragma unroll
        for (int nt = 0; nt < 4; nt++)
#pragma unroll
            for (int j = 0; j < 4; j++) acc[mt][nt][j] = 0.f;

    float4 ra[4], rb[2];
    // prefetch first tile
#pragma unroll
    for (int i = 0; i < 4; i++) {
        int j = tid + 256 * i;                 // A: 128 rows x 8 f4
        ra[i] = *(const float4*)(A + (size_t)(m0 + (j >> 3)) * K + (j & 7) * 4);
    }
#pragma unroll
    for (int i = 0; i < 2; i++) {
        int j = tid + 256 * i;                 // B: 32 rows x 16 f4
        rb[i] = *(const float4*)(Bm + (size_t)(j >> 4) * N + n0 + (j & 15) * 4);
    }

    for (int k0 = 0; k0 < K; k0 += 32) {
        // store (tf32-converted) to smem
#pragma unroll
        for (int i = 0; i < 4; i++) {
            int j = tid + 256 * i;
            float* p = &As[(j >> 3) * ASTR + (j & 7) * 4];
            p[0] = __uint_as_float(f2tf(ra[i].x)); p[1] = __uint_as_float(f2tf(ra[i].y));
            p[2] = __uint_as_float(f2tf(ra[i].z)); p[3] = __uint_as_float(f2tf(ra[i].w));
        }
#pragma unroll
        for (int i = 0; i < 2; i++) {
            int j = tid + 256 * i;
            float* p = &Bs[(j >> 4) * BSTR + (j & 15) * 4];
            p[0] = __uint_as_float(f2tf(rb[i].x)); p[1] = __uint_as_float(f2tf(rb[i].y));
            p[2] = __uint_as_float(f2tf(rb[i].z)); p[3] = __uint_as_float(f2tf(rb[i].w));
        }
        __syncthreads();
        if (k0 + 32 < K) {
#pragma unroll
            for (int i = 0; i < 4; i++) {
                int j = tid + 256 * i;
                ra[i] = *(const float4*)(A + (size_t)(m0 + (j >> 3)) * K + k0 + 32 + (j & 7) * 4);
            }
#pragma unroll
            for (int i = 0; i < 2; i++) {
                int j = tid + 256 * i;
                rb[i] = *(const float4*)(Bm + (size_t)(k0 + 32 + (j >> 4)) * N + n0 + (j & 15) * 4);
            }
        }
#pragma unroll
        for (int c = 0; c < 4; c++) {
            unsigned af[2][4];
#pragma unroll
            for (int mt = 0; mt < 2; mt++) {
                int r = wm + mt * 16 + g;
                af[mt][0] = __float_as_uint(As[r * ASTR + c * 8 + tig]);
                af[mt][1] = __float_as_uint(As[(r + 8) * ASTR + c * 8 + tig]);
                af[mt][2] = __float_as_uint(As[r * ASTR + c * 8 + tig + 4]);
                af[mt][3] = __float_as_uint(As[(r + 8) * ASTR + c * 8 + tig + 4]);
            }
#pragma unroll
            for (int nt = 0; nt < 4; nt++) {
                unsigned bf[2];
                int col = wn + nt * 8 + g;
                bf[0] = __float_as_uint(Bs[(c * 8 + tig) * BSTR + col]);
                bf[1] = __float_as_uint(Bs[(c * 8 + tig + 4) * BSTR + col]);
                mma_tf32(acc[0][nt], af[0], bf);
                mma_tf32(acc[1][nt], af[1], bf);
            }
        }
        __syncthreads();
    }
    // epilogue
#pragma unroll
    for (int mt = 0; mt < 2; mt++) {
#pragma unroll
        for (int nt = 0; nt < 4; nt++) {
            int col = n0 + wn + nt * 8 + 2 * tig;
            float b0 = bias ? bias[col] : 0.f, b1 = bias ? bias[col + 1] : 0.f;
#pragma unroll
            for (int h = 0; h < 2; h++) {
                int row = m0 + wm + mt * 16 + g + 8 * h;
                float v0 = acc[mt][nt][2 * h + 0] + b0;
                float v1 = acc[mt][nt][2 * h + 1] + b1;
                if (resid) {
                    v0 += resid[(size_t)row * N + col];
                    v1 += resid[(size_t)row * N + col + 1];
                }
                C[(size_t)row * N + col]     = v0;
                C[(size_t)row * N + col + 1] = v1;
            }
        }
    }
}

// ---------------- TF32 tensor-core flash MQA attention ----------------
// Grid: (T/64, H, B), 128 threads = 4 warps; warp owns 16 query rows.
#define KSTR 68
#define VSTR 72
#define PSTR 68
#define ATT_SMEM ((64*KSTR + 64*VSTR + 64*PSTR) * 4)
__global__ __launch_bounds__(128) void attn_tc_kernel(
    const float* __restrict__ Q, const float* __restrict__ KV, float* __restrict__ O) {
    extern __shared__ float sm[];
    float* Ks = sm;                       // [key][d]  stride 68
    float* Vs = sm + 64 * KSTR;           // [key][hd] stride 72
    float* Ps = sm + 64 * KSTR + 64 * VSTR; // [qrow][key] stride 68 (warp-private 16-row slices)
    int tid = threadIdx.x;
    int lane = tid & 31, wid = tid >> 5;
    int g = lane >> 2, tig = lane & 3;
    int q0 = blockIdx.x * 64, h = blockIdx.y, b = blockIdx.z;

    // load Q fragments once (scaled by 1/sqrt(64)=0.125, exact)
    unsigned qa[8][4];
    {
        const float* q_lo = Q + ((size_t)(b * TSEQ + q0 + wid * 16 + g)) * FDIM + h * HD;
        const float* q_hi = q_lo + 8 * FDIM;
#pragma unroll
        for (int c = 0; c < 8; c++) {
            qa[c][0] = f2tf(q_lo[c * 8 + tig] * 0.125f);
            qa[c][1] = f2tf(q_hi[c * 8 + tig] * 0.125f);
            qa[c][2] = f2tf(q_lo[c * 8 + tig + 4] * 0.125f);
            qa[c][3] = f2tf(q_hi[c * 8 + tig + 4] * 0.125f);
        }
    }

    float oacc[8][4];
#pragma unroll
    for (int nt = 0; nt < 8; nt++)
#pragma unroll
        for (int j = 0; j < 4; j++) oacc[nt][j] = 0.f;
    float m0r = -1e30f, m1r = -1e30f, l0r = 0.f, l1r = 0.f;

    float* Psw = Ps + wid * 16 * PSTR;
    const float* KVb = KV + (size_t)b * TSEQ * (2 * HD);

    for (int kb = 0; kb < TSEQ / 64; kb++) {
        __syncthreads();  // prior tile's smem reads complete
        // load K/V tile: 64 rows x 32 float4, coalesced; convert to tf32
        const float* Kt = KVb + (size_t)kb * 64 * (2 * HD);
#pragma unroll
        for (int i = 0; i < 16; i++) {
            int j = tid + 128 * i;
            int row = j >> 5, c4 = j & 31;
            float4 v = *(const float4*)(Kt + (size_t)row * (2 * HD) + c4 * 4);
            float* p = (c4 < 16) ? &Ks[row * KSTR + c4 * 4] : &Vs[row * VSTR + (c4 - 16) * 4];
            p[0] = __uint_as_float(f2tf(v.x)); p[1] = __uint_as_float(f2tf(v.y));
            p[2] = __uint_as_float(f2tf(v.z)); p[3] = __uint_as_float(f2tf(v.w));
        }
        __syncthreads();

        // S = Q·K^T  (16 x 64 per warp)
        float sacc[8][4];
#pragma unroll
        for (int nt = 0; nt < 8; nt++)
#pragma unroll
            for (int j = 0; j < 4; j++) sacc[nt][j] = 0.f;
#pragma unroll
        for (int c = 0; c < 8; c++) {
#pragma unroll
            for (int nt = 0; nt < 8; nt++) {
                unsigned bf[2];
                int key = nt * 8 + g;
                bf[0] = __float_as_uint(Ks[key * KSTR + c * 8 + tig]);
                bf[1] = __float_as_uint(Ks[key * KSTR + c * 8 + tig + 4]);
                mma_tf32(sacc[nt], qa[c], bf);
            }
        }

        // online softmax: thread owns rows g (c0,c1) and g+8 (c2,c3)
        float mx0 = -1e30f, mx1 = -1e30f;
#pragma unroll
        for (int nt = 0; nt < 8; nt++) {
            mx0 = fmaxf(mx0, fmaxf(sacc[nt][0], sacc[nt][1]));
            mx1 = fmaxf(mx1, fmaxf(sacc[nt][2], sacc[nt][3]));
        }
        mx0 = fmaxf(mx0, __shfl_xor_sync(0xffffffffu, mx0, 1));
        mx0 = fmaxf(mx0, __shfl_xor_sync(0xffffffffu, mx0, 2));
        mx1 = fmaxf(mx1, __shfl_xor_sync(0xffffffffu, mx1, 1));
        mx1 = fmaxf(mx1, __shfl_xor_sync(0xffffffffu, mx1, 2));
        float mn0 = fmaxf(m0r, mx0), mn1 = fmaxf(m1r, mx1);
        float al0 = __expf(m0r - mn0), al1 = __expf(m1r - mn1);
        m0r = mn0; m1r = mn1;
        float sum0 = 0.f, sum1 = 0.f;
        __syncwarp();  // prior PV reads of Psw done before overwrite
#pragma unroll
        for (int nt = 0; nt < 8; nt++) {
            float p0 = __expf(sacc[nt][0] - mn0), p1 = __expf(sacc[nt][1] - mn0);
            float p2 = __expf(sacc[nt][2] - mn1), p3 = __expf(sacc[nt][3] - mn1);
            sum0 += p0 + p1; sum1 += p2 + p3;
            float* pr0 = &Psw[g * PSTR + nt * 8 + 2 * tig];
            float* pr1 = &Psw[(g + 8) * PSTR + nt * 8 + 2 * tig];
            pr0[0] = __uint_as_float(f2tf(p0)); pr0[1] = __uint_as_float(f2tf(p1));
            pr1[0] = __uint_as_float(f2tf(p2)); pr1[1] = __uint_as_float(f2tf(p3));
        }
        sum0 += __shfl_xor_sync(0xffffffffu, sum0, 1);
        sum0 += __shfl_xor_sync(0xffffffffu, sum0, 2);
        sum1 += __shfl_xor_sync(0xffffffffu, sum1, 1);
        sum1 += __shfl_xor_sync(0xffffffffu, sum1, 2);
        l0r = l0r * al0 + sum0; l1r = l1r * al1 + sum1;
#pragma unroll
        for (int nt = 0; nt < 8; nt++) {
            oacc[nt][0] *= al0; oacc[nt][1] *= al0;
            oacc[nt][2] *= al1; oacc[nt][3] *= al1;
        }
        __syncwarp();  // Psw visible to all lanes of warp

        // O += P·V
#pragma unroll
        for (int c = 0; c < 8; c++) {
            unsigned pa[4];
            pa[0] = __float_as_uint(Psw[g * PSTR + c * 8 + tig]);
            pa[1] = __float_as_uint(Psw[(g + 8) * PSTR + c * 8 + tig]);
            pa[2] = __float_as_uint(Psw[g * PSTR + c * 8 + tig + 4]);
            pa[3] = __float_as_uint(Psw[(g + 8) * PSTR + c * 8 + tig + 4]);
#pragma unroll
            for (int nt = 0; nt < 8; nt++) {
                unsigned bf[2];
                int col = nt * 8 + g;
                bf[0] = __float_as_uint(Vs[(c * 8 + tig) * VSTR + col]);
                bf[1] = __float_as_uint(Vs[(c * 8 + tig + 4) * VSTR + col]);
                mma_tf32(oacc[nt], pa, bf);
            }
        }
    }

    // write O
    float inv0 = 1.f / l0r, inv1 = 1.f / l1r;
    float* o_lo = O + ((size_t)(b * TSEQ + q0 + wid * 16 + g)) * FDIM + h * HD;
    float* o_hi = o_lo + 8 * FDIM;
#pragma unroll
    for (int nt = 0; nt < 8; nt++) {
        int col = nt * 8 + 2 * tig;
        o_lo[col]     = oacc[nt][0] * inv0;
        o_lo[col + 1] = oacc[nt][1] * inv0;
        o_hi[col]     = oacc[nt][2] * inv1;
        o_hi[col + 1] = oacc[nt][3] * inv1;
    }
}

extern "C" void kernel_launch(void* const* d_in, const int* in_sizes, int n_in,
                              void* d_out, int out_size) {
    (void)in_sizes; (void)n_in; (void)out_size;
    const float* x     = (const float*)d_in[0];
    const float* gamma = (const float*)d_in[1];
    const float* beta  = (const float*)d_in[2];
    const float* Wq    = (const float*)d_in[3];
    const float* Wkv   = (const float*)d_in[4];
    const float* Wo    = (const float*)d_in[5];
    const float* bo    = (const float*)d_in[6];
    float* out = (float*)d_out;

    float *xn, *q, *kv, *att;
    cudaGetSymbolAddress((void**)&xn,  g_xn);
    cudaGetSymbolAddress((void**)&q,   g_q);
    cudaGetSymbolAddress((void**)&kv,  g_kv);
    cudaGetSymbolAddress((void**)&att, g_att);

    ln_kernel<<<ROWS, 256>>>(x, gamma, beta, xn);

    gemm_tc_kernel<<<dim3(FDIM / 64, ROWS / 128), 256>>>(xn, Wq, q, ROWS, FDIM, FDIM, nullptr, nullptr);
    gemm_tc_kernel<<<dim3((2 * HD) / 64, ROWS / 128), 256>>>(xn, Wkv, kv, ROWS, 2 * HD, FDIM, nullptr, nullptr);

    cudaFuncSetAttribute(attn_tc_kernel, cudaFuncAttributeMaxDynamicSharedMemorySize, ATT_SMEM);
    attn_tc_kernel<<<dim3(TSEQ / 64, NH, BATCH), 128, ATT_SMEM>>>(q, kv, att);

    gemm_tc_kernel<<<dim3(FDIM / 64, ROWS / 128), 256>>>(att, Wo, out, ROWS, FDIM, FDIM, bo, x);
}

// round 3
// speedup vs baseline: 3.9152x; 1.3137x over previous
#include <cuda_runtime.h>
#include <cuda_bf16.h>
#include <math.h>

#define FDIM 1024
#define TSEQ 2048
#define BATCH 2
#define NH 16
#define HD 64
#define ROWS (BATCH*TSEQ)   // 4096

// scratch (allocation-free rule: __device__ globals)
__device__ float g_xn[ROWS*FDIM];
__device__ float g_q[ROWS*FDIM];
__device__ float g_kv[ROWS*2*HD];
__device__ float g_att[ROWS*FDIM];

// ---------- helpers ----------
__device__ __forceinline__ unsigned f2tf(float f) {
    unsigned u; asm("cvt.rna.tf32.f32 %0, %1;" : "=r"(u) : "f"(f)); return u;
}
__device__ __forceinline__ void mma_tf32(float* c, const unsigned* a, const unsigned* b) {
    asm volatile(
        "mma.sync.aligned.m16n8k8.row.col.f32.tf32.tf32.f32 "
        "{%0,%1,%2,%3},{%4,%5,%6,%7},{%8,%9},{%0,%1,%2,%3};"
        : "+f"(c[0]), "+f"(c[1]), "+f"(c[2]), "+f"(c[3])
        : "r"(a[0]), "r"(a[1]), "r"(a[2]), "r"(a[3]), "r"(b[0]), "r"(b[1]));
}
__device__ __forceinline__ unsigned packbf(float lo, float hi) {
    unsigned r; asm("cvt.rn.bf16x2.f32 %0, %1, %2;" : "=r"(r) : "f"(hi), "f"(lo)); return r;
}
__device__ __forceinline__ void mma_bf16(float* c, const unsigned* a, unsigned b0, unsigned b1) {
    asm volatile(
        "mma.sync.aligned.m16n8k16.row.col.f32.bf16.bf16.f32 "
        "{%0,%1,%2,%3},{%4,%5,%6,%7},{%8,%9},{%0,%1,%2,%3};"
        : "+f"(c[0]), "+f"(c[1]), "+f"(c[2]), "+f"(c[3])
        : "r"(a[0]), "r"(a[1]), "r"(a[2]), "r"(a[3]), "r"(b0), "r"(b1));
}
__device__ __forceinline__ void ldmx4(unsigned& r0, unsigned& r1, unsigned& r2, unsigned& r3, unsigned addr) {
    asm volatile("ldmatrix.sync.aligned.m8n8.x4.shared.b16 {%0,%1,%2,%3}, [%4];"
        : "=r"(r0), "=r"(r1), "=r"(r2), "=r"(r3) : "r"(addr));
}
__device__ __forceinline__ void ldmx4t(unsigned& r0, unsigned& r1, unsigned& r2, unsigned& r3, unsigned addr) {
    asm volatile("ldmatrix.sync.aligned.m8n8.x4.trans.shared.b16 {%0,%1,%2,%3}, [%4];"
        : "=r"(r0), "=r"(r1), "=r"(r2), "=r"(r3) : "r"(addr));
}

// ---------------- LayerNorm ----------------
__global__ void ln_kernel(const float* __restrict__ x, const float* __restrict__ gamma,
                          const float* __restrict__ beta, float* __restrict__ xn) {
    int row = blockIdx.x;
    const float* xr = x + (size_t)row * FDIM;
    float s = 0.f, s2 = 0.f;
    for (int i = threadIdx.x; i < FDIM; i += 256) { float v = xr[i]; s += v; s2 += v * v; }
    __shared__ float rs[8], rs2[8];
    for (int o = 16; o > 0; o >>= 1) {
        s  += __shfl_xor_sync(0xffffffffu, s,  o);
        s2 += __shfl_xor_sync(0xffffffffu, s2, o);
    }
    int w = threadIdx.x >> 5;
    if ((threadIdx.x & 31) == 0) { rs[w] = s; rs2[w] = s2; }
    __syncthreads();
    if (threadIdx.x < 32) {
        s  = (threadIdx.x < 8) ? rs[threadIdx.x]  : 0.f;
        s2 = (threadIdx.x < 8) ? rs2[threadIdx.x] : 0.f;
        for (int o = 4; o > 0; o >>= 1) {
            s  += __shfl_xor_sync(0xffffffffu, s,  o);
            s2 += __shfl_xor_sync(0xffffffffu, s2, o);
        }
        if (threadIdx.x == 0) { rs[0] = s; rs2[0] = s2; }
    }
    __syncthreads();
    float mu  = rs[0] * (1.f / FDIM);
    float var = rs2[0] * (1.f / FDIM) - mu * mu;
    float inv = rsqrtf(var + 1e-5f);
    float* xo = xn + (size_t)row * FDIM;
    for (int i = threadIdx.x; i < FDIM; i += 256)
        xo[i] = (xr[i] - mu) * inv * gamma[i] + beta[i];
}

// ---------------- TF32 tensor-core GEMM (unchanged from round 2) ----------------
#define ASTR 36
#define BSTR 72
__global__ __launch_bounds__(256) void gemm_tc_kernel(
    const float* __restrict__ A, const float* __restrict__ Bm,
    float* __restrict__ C, int M, int N, int K,
    const float* __restrict__ bias, const float* __restrict__ resid) {
    __shared__ float As[128 * ASTR];
    __shared__ float Bs[32 * BSTR];
    int tid = threadIdx.x;
    int lane = tid & 31, wid = tid >> 5;
    int g = lane >> 2, tig = lane & 3;
    int wm = (wid & 3) * 32, wn = (wid >> 2) * 32;
    int m0 = blockIdx.y * 128, n0 = blockIdx.x * 64;

    float acc[2][4][4];
#pragma unroll
    for (int mt = 0; mt < 2; mt++)
#pragma unroll
        for (int nt = 0; nt < 4; nt++)
#pragma unroll
            for (int j = 0; j < 4; j++) acc[mt][nt][j] = 0.f;

    float4 ra[4], rb[2];
#pragma unroll
    for (int i = 0; i < 4; i++) {
        int j = tid + 256 * i;
        ra[i] = *(const float4*)(A + (size_t)(m0 + (j >> 3)) * K + (j & 7) * 4);
    }
#pragma unroll
    for (int i = 0; i < 2; i++) {
        int j = tid + 256 * i;
        rb[i] = *(const float4*)(Bm + (size_t)(j >> 4) * N + n0 + (j & 15) * 4);
    }

    for (int k0 = 0; k0 < K; k0 += 32) {
#pragma unroll
        for (int i = 0; i < 4; i++) {
            int j = tid + 256 * i;
            float* p = &As[(j >> 3) * ASTR + (j & 7) * 4];
            p[0] = __uint_as_float(f2tf(ra[i].x)); p[1] = __uint_as_float(f2tf(ra[i].y));
            p[2] = __uint_as_float(f2tf(ra[i].z)); p[3] = __uint_as_float(f2tf(ra[i].w));
        }
#pragma unroll
        for (int i = 0; i < 2; i++) {
            int j = tid + 256 * i;
            float* p = &Bs[(j >> 4) * BSTR + (j & 15) * 4];
            p[0] = __uint_as_float(f2tf(rb[i].x)); p[1] = __uint_as_float(f2tf(rb[i].y));
            p[2] = __uint_as_float(f2tf(rb[i].z)); p[3] = __uint_as_float(f2tf(rb[i].w));
        }
        __syncthreads();
        if (k0 + 32 < K) {
#pragma unroll
            for (int i = 0; i < 4; i++) {
                int j = tid + 256 * i;
                ra[i] = *(const float4*)(A + (size_t)(m0 + (j >> 3)) * K + k0 + 32 + (j & 7) * 4);
            }
#pragma unroll
            for (int i = 0; i < 2; i++) {
                int j = tid + 256 * i;
                rb[i] = *(const float4*)(Bm + (size_t)(k0 + 32 + (j >> 4)) * N + n0 + (j & 15) * 4);
            }
        }
#pragma unroll
        for (int c = 0; c < 4; c++) {
            unsigned af[2][4];
#pragma unroll
            for (int mt = 0; mt < 2; mt++) {
                int r = wm + mt * 16 + g;
                af[mt][0] = __float_as_uint(As[r * ASTR + c * 8 + tig]);
                af[mt][1] = __float_as_uint(As[(r + 8) * ASTR + c * 8 + tig]);
                af[mt][2] = __float_as_uint(As[r * ASTR + c * 8 + tig + 4]);
                af[mt][3] = __float_as_uint(As[(r + 8) * ASTR + c * 8 + tig + 4]);
            }
#pragma unroll
            for (int nt = 0; nt < 4; nt++) {
                unsigned bf[2];
                int col = wn + nt * 8 + g;
                bf[0] = __float_as_uint(Bs[(c * 8 + tig) * BSTR + col]);
                bf[1] = __float_as_uint(Bs[(c * 8 + tig + 4) * BSTR + col]);
                mma_tf32(acc[0][nt], af[0], bf);
                mma_tf32(acc[1][nt], af[1], bf);
            }
        }
        __syncthreads();
    }
#pragma unroll
    for (int mt = 0; mt < 2; mt++) {
#pragma unroll
        for (int nt = 0; nt < 4; nt++) {
            int col = n0 + wn + nt * 8 + 2 * tig;
            float b0 = bias ? bias[col] : 0.f, b1 = bias ? bias[col + 1] : 0.f;
#pragma unroll
            for (int h = 0; h < 2; h++) {
                int row = m0 + wm + mt * 16 + g + 8 * h;
                float v0 = acc[mt][nt][2 * h + 0] + b0;
                float v1 = acc[mt][nt][2 * h + 1] + b1;
                if (resid) {
                    v0 += resid[(size_t)row * N + col];
                    v1 += resid[(size_t)row * N + col + 1];
                }
                C[(size_t)row * N + col]     = v0;
                C[(size_t)row * N + col + 1] = v1;
            }
        }
    }
}

// ---------------- bf16 m16n8k16 + ldmatrix flash MQA attention ----------------
// Grid: (T/64, H, B), 128 threads = 4 warps; warp owns 16 query rows.
// smem rows stride 144B (72 bf16) -> 4-bank rotation per row, conflict-free ldmatrix.
#define RSTRB 144
#define SM_K 0
#define SM_V (64*RSTRB)          // 9216
#define SM_P (2*64*RSTRB)        // 18432 .. +9216 = 27648 total
#define ATT_SMEM (3*64*RSTRB)
__global__ __launch_bounds__(128) void attn_bf_kernel(
    const float* __restrict__ Q, const float* __restrict__ KV, float* __restrict__ O) {
    extern __shared__ char sm[];
    int tid = threadIdx.x;
    int lane = tid & 31, wid = tid >> 5;
    int g = lane >> 2, tig = lane & 3;
    int grp = lane >> 3, r8 = lane & 7;
    int q0 = blockIdx.x * 64, h = blockIdx.y, b = blockIdx.z;

    // Q fragments (bf16, pre-scaled by 1/8 = exact)
    unsigned qa[4][4];
    {
        const float2* qlo = (const float2*)(Q + ((size_t)(b * TSEQ + q0 + wid * 16 + g)) * FDIM + h * HD);
        const float2* qhi = qlo + 4 * FDIM;  // +8 rows (float2 units)
#pragma unroll
        for (int kc = 0; kc < 4; kc++) {
            float2 a = qlo[kc * 8 + tig], b2 = qhi[kc * 8 + tig];
            float2 c = qlo[kc * 8 + 4 + tig], d = qhi[kc * 8 + 4 + tig];
            qa[kc][0] = packbf(a.x * 0.125f, a.y * 0.125f);
            qa[kc][1] = packbf(b2.x * 0.125f, b2.y * 0.125f);
            qa[kc][2] = packbf(c.x * 0.125f, c.y * 0.125f);
            qa[kc][3] = packbf(d.x * 0.125f, d.y * 0.125f);
        }
    }

    unsigned smbase = (unsigned)__cvta_generic_to_shared(sm);
    // ldmatrix per-thread base addresses
    unsigned kaddr = smbase + SM_K + (unsigned)(((grp >> 1) * 8 + r8) * RSTRB + (grp & 1) * 16);
    unsigned vaddr = smbase + SM_V + (unsigned)(((grp & 1) * 8 + r8) * RSTRB + (grp >> 1) * 16);
    unsigned paddr = smbase + SM_P + (unsigned)(wid * 16 * RSTRB + ((grp & 1) * 8 + r8) * RSTRB + (grp >> 1) * 16);
    unsigned* psw = (unsigned*)(sm + SM_P + wid * 16 * RSTRB);

    float oacc[8][4];
#pragma unroll
    for (int nt = 0; nt < 8; nt++)
#pragma unroll
        for (int j = 0; j < 4; j++) oacc[nt][j] = 0.f;
    float m0r = -1e30f, m1r = -1e30f, l0r = 0.f, l1r = 0.f;

    const float* KVb = KV + (size_t)b * TSEQ * (2 * HD);

    for (int kb = 0; kb < TSEQ / 64; kb++) {
        __syncthreads();  // previous tile's smem reads complete
        // load K/V tile (64 rows x 128 floats), convert to bf16, natural layouts
        const float* Kt = KVb + (size_t)kb * 64 * (2 * HD);
#pragma unroll
        for (int i = 0; i < 16; i++) {
            int j = tid + 128 * i;
            int row = j >> 5, c4 = j & 31;
            float4 v = *(const float4*)(Kt + (size_t)row * (2 * HD) + c4 * 4);
            uint2 u = make_uint2(packbf(v.x, v.y), packbf(v.z, v.w));
            char* dst = (c4 < 16) ? (sm + SM_K + row * RSTRB + c4 * 8)
                                  : (sm + SM_V + row * RSTRB + (c4 - 16) * 8);
            *(uint2*)dst = u;
        }
        __syncthreads();

        // S = Q.K^T  (16 x 64 per warp)
        float sacc[8][4];
#pragma unroll
        for (int nt = 0; nt < 8; nt++)
#pragma unroll
            for (int j = 0; j < 4; j++) sacc[nt][j] = 0.f;
#pragma unroll
        for (int kc = 0; kc < 4; kc++) {
#pragma unroll
            for (int p = 0; p < 4; p++) {
                unsigned b0, b1, b2, b3;
                ldmx4(b0, b1, b2, b3, kaddr + p * (16 * RSTRB) + kc * 32);
                mma_bf16(sacc[2 * p],     qa[kc], b0, b1);
                mma_bf16(sacc[2 * p + 1], qa[kc], b2, b3);
            }
        }

        // online softmax: thread owns rows g (c0,c1) and g+8 (c2,c3)
        float mx0 = -1e30f, mx1 = -1e30f;
#pragma unroll
        for (int nt = 0; nt < 8; nt++) {
            mx0 = fmaxf(mx0, fmaxf(sacc[nt][0], sacc[nt][1]));
            mx1 = fmaxf(mx1, fmaxf(sacc[nt][2], sacc[nt][3]));
        }
        mx0 = fmaxf(mx0, __shfl_xor_sync(0xffffffffu, mx0, 1));
        mx0 = fmaxf(mx0, __shfl_xor_sync(0xffffffffu, mx0, 2));
        mx1 = fmaxf(mx1, __shfl_xor_sync(0xffffffffu, mx1, 1));
        mx1 = fmaxf(mx1, __shfl_xor_sync(0xffffffffu, mx1, 2));
        float mn0 = fmaxf(m0r, mx0), mn1 = fmaxf(m1r, mx1);
        float al0 = __expf(m0r - mn0), al1 = __expf(m1r - mn1);
        m0r = mn0; m1r = mn1;
        float sum0 = 0.f, sum1 = 0.f;
#pragma unroll
        for (int nt = 0; nt < 8; nt++) {
            float p0 = __expf(sacc[nt][0] - mn0), p1 = __expf(sacc[nt][1] - mn0);
            float p2 = __expf(sacc[nt][2] - mn1), p3 = __expf(sacc[nt][3] - mn1);
            sum0 += p0 + p1; sum1 += p2 + p3;
            psw[g * 36 + nt * 4 + tig]       = packbf(p0, p1);
            psw[(g + 8) * 36 + nt * 4 + tig] = packbf(p2, p3);
        }
        sum0 += __shfl_xor_sync(0xffffffffu, sum0, 1);
        sum0 += __shfl_xor_sync(0xffffffffu, sum0, 2);
        sum1 += __shfl_xor_sync(0xffffffffu, sum1, 1);
        sum1 += __shfl_xor_sync(0xffffffffu, sum1, 2);
        l0r = l0r * al0 + sum0; l1r = l1r * al1 + sum1;
#pragma unroll
        for (int nt = 0; nt < 8; nt++) {
            oacc[nt][0] *= al0; oacc[nt][1] *= al0;
            oacc[nt][2] *= al1; oacc[nt][3] *= al1;
        }
        __syncwarp();  // P visible to warp before ldmatrix

        // O += P.V
#pragma unroll
        for (int kc = 0; kc < 4; kc++) {
            unsigned pa[4];
            ldmx4(pa[0], pa[1], pa[2], pa[3], paddr + kc * 32);
#pragma unroll
            for (int p = 0; p < 4; p++) {
                unsigned v0, v1, v2, v3;
                ldmx4t(v0, v1, v2, v3, vaddr + kc * (16 * RSTRB) + p * 32);
                mma_bf16(oacc[2 * p],     pa, v0, v1);
                mma_bf16(oacc[2 * p + 1], pa, v2, v3);
            }
        }
    }

    // write O
    float inv0 = 1.f / l0r, inv1 = 1.f / l1r;
    float* o_lo = O + ((size_t)(b * TSEQ + q0 + wid * 16 + g)) * FDIM + h * HD;
    float* o_hi = o_lo + 8 * FDIM;
#pragma unroll
    for (int nt = 0; nt < 8; nt++) {
        int col = nt * 8 + 2 * tig;
        o_lo[col]     = oacc[nt][0] * inv0;
        o_lo[col + 1] = oacc[nt][1] * inv0;
        o_hi[col]     = oacc[nt][2] * inv1;
        o_hi[col + 1] = oacc[nt][3] * inv1;
    }
}

extern "C" void kernel_launch(void* const* d_in, const int* in_sizes, int n_in,
                              void* d_out, int out_size) {
    (void)in_sizes; (void)n_in; (void)out_size;
    const float* x     = (const float*)d_in[0];
    const float* gamma = (const float*)d_in[1];
    const float* beta  = (const float*)d_in[2];
    const float* Wq    = (const float*)d_in[3];
    const float* Wkv   = (const float*)d_in[4];
    const float* Wo    = (const float*)d_in[5];
    const float* bo    = (const float*)d_in[6];
    float* out = (float*)d_out;

    float *xn, *q, *kv, *att;
    cudaGetSymbolAddress((void**)&xn,  g_xn);
    cudaGetSymbolAddress((void**)&q,   g_q);
    cudaGetSymbolAddress((void**)&kv,  g_kv);
    cudaGetSymbolAddress((void**)&att, g_att);

    ln_kernel<<<ROWS, 256>>>(x, gamma, beta, xn);

    gemm_tc_kernel<<<dim3(FDIM / 64, ROWS / 128), 256>>>(xn, Wq, q, ROWS, FDIM, FDIM, nullptr, nullptr);
    gemm_tc_kernel<<<dim3((2 * HD) / 64, ROWS / 128), 256>>>(xn, Wkv, kv, ROWS, 2 * HD, FDIM, nullptr, nullptr);

    cudaFuncSetAttribute(attn_bf_kernel, cudaFuncAttributeMaxDynamicSharedMemorySize, ATT_SMEM);
    attn_bf_kernel<<<dim3(TSEQ / 64, NH, BATCH), 128, ATT_SMEM>>>(q, kv, att);

    gemm_tc_kernel<<<dim3(FDIM / 64, ROWS / 128), 256>>>(att, Wo, out, ROWS, FDIM, FDIM, bo, x);
}